// round 14
// baseline (speedup 1.0000x reference)
#include <cuda_runtime.h>
#include <cuda_bf16.h>
#include <cstdint>

#define D      128
#define NROW   50000
#define NCOL   50000
#define NTOT   (NROW + NCOL)
#define BM     64
#define NSLAB  ((NROW + BM - 1) / BM)     // 782 (same for NCOL)

// X tile: 64 rows x 128 k bf16, row stride 272B
#define LDB_B   272
#define XTILE_B (64 * LDB_B)          // 17408
// W half-tile: 128 n-rows x 64 k bf16, row stride 144B
#define LDW_B   144
#define WHALF_B (128 * LDW_B)         // 18432
#define WHALF_U4 (WHALF_B / 16)       // 1152

// Scratch (alloc-free rule: __device__ globals)
__device__ float g_hrow[(size_t)NROW * D];
__device__ uint4 g_xt[(size_t)NSLAB * 2 * XTILE_B / 16];   // bf16 hi/lo X tiles (reused per phase)
__device__ uint4 g_wt[4][2][2][WHALF_U4];   // [matrix][khalf][hi/lo]
__device__ int   g_cnt[NTOT];
__device__ int   g_ptr[NTOT + 1];
__device__ int   g_bsum[128];
__device__ int   g_flag;
__device__ int2  g_edges[1200000];

__device__ __forceinline__ float leaky(float v) { return v >= 0.f ? v : 0.01f * v; }

// ---------------- weight pre-split + counter zero (merged prep) ----------------
static __device__ __forceinline__ void split8(const float* x, uint32_t* hi, uint32_t* lo) {
    #pragma unroll
    for (int j = 0; j < 4; j++) {
        __nv_bfloat16 h0 = __float2bfloat16(x[2*j]);
        __nv_bfloat16 h1 = __float2bfloat16(x[2*j+1]);
        __nv_bfloat16 l0 = __float2bfloat16(x[2*j]   - __bfloat162float(h0));
        __nv_bfloat16 l1 = __float2bfloat16(x[2*j+1] - __bfloat162float(h1));
        hi[j] = (uint32_t)__bfloat16_as_ushort(h0) | ((uint32_t)__bfloat16_as_ushort(h1) << 16);
        lo[j] = (uint32_t)__bfloat16_as_ushort(l0) | ((uint32_t)__bfloat16_as_ushort(l1) << 16);
    }
}

static __device__ __forceinline__ void split2(float x0, float x1, uint32_t& hi, uint32_t& lo) {
    __nv_bfloat16 h0 = __float2bfloat16(x0);
    __nv_bfloat16 h1 = __float2bfloat16(x1);
    __nv_bfloat16 l0 = __float2bfloat16(x0 - __bfloat162float(h0));
    __nv_bfloat16 l1 = __float2bfloat16(x1 - __bfloat162float(h1));
    hi = (uint32_t)__bfloat16_as_ushort(h0) | ((uint32_t)__bfloat16_as_ushort(h1) << 16);
    lo = (uint32_t)__bfloat16_as_ushort(l0) | ((uint32_t)__bfloat16_as_ushort(l1) << 16);
}

__global__ void prep_kernel(const float* __restrict__ Wa, const float* __restrict__ Wb,
                            const float* __restrict__ Wc, const float* __restrict__ Wd,
                            int* __restrict__ cnt, int* __restrict__ flag) {
    int task = blockIdx.x * blockDim.x + threadIdx.x;   // 0..8191
    for (int i = task; i < NTOT; i += 8192) cnt[i] = 0;
    if (task == 0) *flag = 0;
    int m = task >> 11;
    int tt = task & 2047;
    int n = tt & 127, kg = tt >> 7;
    const float* W = (m == 0) ? Wa : (m == 1) ? Wb : (m == 2) ? Wc : Wd;
    float v[8];
    #pragma unroll
    for (int j = 0; j < 8; j++) v[j] = __ldg(W + (kg * 8 + j) * D + n);
    uint32_t hi[4], lo[4];
    split8(v, hi, lo);
    int half = kg >> 3, kgl = kg & 7;
    int idx = n * 9 + kgl;
    g_wt[m][half][0][idx] = make_uint4(hi[0], hi[1], hi[2], hi[3]);
    g_wt[m][half][1][idx] = make_uint4(lo[0], lo[1], lo[2], lo[3]);
}

// ---------------- CSR build ----------------
__global__ void hist2_kernel(const int* __restrict__ dst1, const int* __restrict__ dst2,
                             int* __restrict__ cnt, int E) {
    int e = blockIdx.x * blockDim.x + threadIdx.x;
    if (e >= 2 * E) return;
    if (e < E) atomicAdd(cnt + __ldg(dst1 + e), 1);
    else       atomicAdd(cnt + NROW + __ldg(dst2 + e - E), 1);
}

// block-local exclusive scan + block totals; LAST block scans the totals and
// writes ptr[NTOT] = total.
__global__ void scan_blk_kernel(const int* __restrict__ cnt, int* __restrict__ ptr,
                                int* __restrict__ bsum, int* __restrict__ flag, int n) {
    __shared__ int wsum[32];
    __shared__ int tmp[128];
    __shared__ int is_last;
    int tid = threadIdx.x, lane = tid & 31, wid = tid >> 5;
    int i = blockIdx.x * 1024 + tid;
    int x = (i < n) ? cnt[i] : 0;
    int v = x;
    #pragma unroll
    for (int o = 1; o < 32; o <<= 1) { int t = __shfl_up_sync(~0u, v, o); if (lane >= o) v += t; }
    if (lane == 31) wsum[wid] = v;
    __syncthreads();
    if (wid == 0) {
        int s = wsum[lane];
        #pragma unroll
        for (int o = 1; o < 32; o <<= 1) { int t = __shfl_up_sync(~0u, s, o); if (lane >= o) s += t; }
        wsum[lane] = s;
    }
    __syncthreads();
    int woff = wid ? wsum[wid - 1] : 0;
    if (i < n) ptr[i] = woff + v - x;

    if (tid == 0) {
        bsum[blockIdx.x] = wsum[31];
        __threadfence();
        int old = atomicAdd(flag, 1);
        is_last = (old == (int)gridDim.x - 1) ? 1 : 0;
    }
    __syncthreads();
    if (is_last) {
        __threadfence();
        int nb = gridDim.x;                 // <= 128
        int xx = (tid < nb) ? bsum[tid] : 0;
        if (tid < 128) tmp[tid] = xx;
        __syncthreads();
        for (int o = 1; o < 128; o <<= 1) {
            int t = (tid >= o && tid < 128) ? tmp[tid - o] : 0;
            __syncthreads();
            if (tid < 128) tmp[tid] += t;
            __syncthreads();
        }
        if (tid < nb) bsum[tid] = tmp[tid] - xx;    // exclusive block offsets
        if (tid == nb - 1) ptr[n] = tmp[tid];       // total = inclusive last
    }
}

// final position of node i: ptr[i] + bsum[i>>10]; cnt[i] used as countdown
__global__ void scatter2_kernel(const int* __restrict__ src1, const int* __restrict__ dst1,
                                const float* __restrict__ w1,
                                const int* __restrict__ src2, const int* __restrict__ dst2,
                                const float* __restrict__ w2,
                                const int* __restrict__ ptr, const int* __restrict__ bsum,
                                int* __restrict__ cnt, int2* __restrict__ edges, int E) {
    int e = blockIdx.x * blockDim.x + threadIdx.x;
    if (e >= 2 * E) return;
    int d, s;
    float w;
    if (e < E) {
        d = __ldg(dst1 + e);
        s = __ldg(src1 + e);
        w = __ldg(w1 + e);
    } else {
        d = NROW + __ldg(dst2 + e - E);
        s = __ldg(src2 + e - E);
        w = __ldg(w2 + e - E);
    }
    int base = __ldg(ptr + d) + __ldg(bsum + (d >> 10));
    int pos = base + atomicSub(cnt + d, 1) - 1;
    edges[pos] = make_int2(s, __float_as_int(w));
}

// ---------------- CSR aggregation + X split: one warp per dst node ----------------
// Computes x = (1+eps)*feat_self + sum(w*feat_src[src]) and writes bf16 hi/lo
// directly into the mlp's X-tile layout in global memory.
__global__ void csr_agg_kernel(const float4* __restrict__ feat_src,
                               const float4* __restrict__ feat_self,
                               const int* __restrict__ ptr, const int* __restrict__ bsum,
                               const int2* __restrict__ edges,
                               uint4* __restrict__ xt,
                               const float* __restrict__ eps_p, int n, int off) {
    int t = blockIdx.x * blockDim.x + threadIdx.x;
    int node = t >> 5;
    if (node >= n) return;
    int lane = t & 31;
    int i0 = off + node;
    int i1 = i0 + 1;
    int beg = __ldg(ptr + i0) + __ldg(bsum + (i0 >> 10));
    int end = (i1 == NTOT) ? __ldg(ptr + NTOT)
                           : __ldg(ptr + i1) + __ldg(bsum + (i1 >> 10));
    float4 a0 = make_float4(0.f, 0.f, 0.f, 0.f);
    float4 a1 = make_float4(0.f, 0.f, 0.f, 0.f);
    int i = beg;
    for (; i + 2 <= end; i += 2) {
        int2 e0 = __ldg(edges + i);
        int2 e1 = __ldg(edges + i + 1);
        float w0 = __int_as_float(e0.y), w1 = __int_as_float(e1.y);
        float4 v0 = __ldg(feat_src + (size_t)e0.x * 32 + lane);
        float4 v1 = __ldg(feat_src + (size_t)e1.x * 32 + lane);
        a0.x = fmaf(v0.x, w0, a0.x); a0.y = fmaf(v0.y, w0, a0.y);
        a0.z = fmaf(v0.z, w0, a0.z); a0.w = fmaf(v0.w, w0, a0.w);
        a1.x = fmaf(v1.x, w1, a1.x); a1.y = fmaf(v1.y, w1, a1.y);
        a1.z = fmaf(v1.z, w1, a1.z); a1.w = fmaf(v1.w, w1, a1.w);
    }
    if (i < end) {
        int2 e0 = __ldg(edges + i);
        float w0 = __int_as_float(e0.y);
        float4 v0 = __ldg(feat_src + (size_t)e0.x * 32 + lane);
        a0.x = fmaf(v0.x, w0, a0.x); a0.y = fmaf(v0.y, w0, a0.y);
        a0.z = fmaf(v0.z, w0, a0.z); a0.w = fmaf(v0.w, w0, a0.w);
    }
    float eps1 = 1.f + __ldg(eps_p);
    float4 f = __ldg(feat_self + (size_t)node * 32 + lane);
    float4 v;
    v.x = fmaf(eps1, f.x, a0.x + a1.x);
    v.y = fmaf(eps1, f.y, a0.y + a1.y);
    v.z = fmaf(eps1, f.z, a0.z + a1.z);
    v.w = fmaf(eps1, f.w, a0.w + a1.w);
    uint32_t h01, l01, h23, l23;
    split2(v.x, v.y, h01, l01);
    split2(v.z, v.w, h23, l23);
    int slab = node >> 6, r = node & 63;
    char* base = (char*)xt + (size_t)slab * (2 * XTILE_B);
    uint32_t o = (uint32_t)r * LDB_B + (uint32_t)lane * 8;
    *(uint2*)(base + o) = make_uint2(h01, h23);
    *(uint2*)(base + XTILE_B + o) = make_uint2(l01, l23);
}

// ---------------- HMMA (mma.sync) MLP, pipelined W halves ----------------
#define SM_XHI  0
#define SM_XLO  (SM_XHI + XTILE_B)
#define SM_WS0  (SM_XLO + XTILE_B)
#define SM_WS1  (SM_WS0 + WHALF_B)
#define SM_WS2  (SM_WS1 + WHALF_B)
#define SM_WS3  (SM_WS2 + WHALF_B)
#define SM_B1   (SM_WS3 + WHALF_B)
#define SM_B2   (SM_B1 + 512)
#define SM_TOTAL (SM_B2 + 512)            // 109568 -> 2 CTAs/SM
#define SM_FST  SM_WS0
#define LDF     132

static __device__ __forceinline__ uint32_t smem_u32(const void* p) {
    uint32_t a;
    asm("{ .reg .u64 t; cvta.to.shared.u64 t, %1; cvt.u32.u64 %0, t; }" : "=r"(a) : "l"(p));
    return a;
}

static __device__ __forceinline__ void ldsm4(uint32_t* r, uint32_t addr) {
    asm volatile("ldmatrix.sync.aligned.m8n8.x4.shared.b16 {%0,%1,%2,%3}, [%4];"
                 : "=r"(r[0]), "=r"(r[1]), "=r"(r[2]), "=r"(r[3]) : "r"(addr));
}

static __device__ __forceinline__ void mma16816(float* d, const uint32_t* a,
                                                uint32_t b0, uint32_t b1) {
    asm volatile("mma.sync.aligned.m16n8k16.row.col.f32.bf16.bf16.f32 "
                 "{%0,%1,%2,%3}, {%4,%5,%6,%7}, {%8,%9}, {%0,%1,%2,%3};"
                 : "+f"(d[0]), "+f"(d[1]), "+f"(d[2]), "+f"(d[3])
                 : "r"(a[0]), "r"(a[1]), "r"(a[2]), "r"(a[3]), "r"(b0), "r"(b1));
}

static __device__ __forceinline__ void stage_whalf(uint32_t smb, uint32_t hi_off, uint32_t lo_off,
                                                   const uint4* __restrict__ half_base, int tid) {
    const uint4* hi = half_base;
    const uint4* lo = half_base + WHALF_U4;
    for (int i = tid; i < WHALF_U4; i += 256) {
        asm volatile("cp.async.cg.shared.global [%0], [%1], 16;"
                     :: "r"(smb + hi_off + (uint32_t)i * 16), "l"(hi + i));
        asm volatile("cp.async.cg.shared.global [%0], [%1], 16;"
                     :: "r"(smb + lo_off + (uint32_t)i * 16), "l"(lo + i));
    }
    asm volatile("cp.async.commit_group;" ::: "memory");
}
template <int N>
static __device__ __forceinline__ void wait_cp_n() {
    asm volatile("cp.async.wait_group %0;" :: "n"(N) : "memory");
}

// one k-half of a layer, 2x4 warp grid (R13 version)
static __device__ __forceinline__ void do_half(uint32_t smb, uint32_t whi, uint32_t wlo,
                                               int khalf, int mg, int ng, int lane,
                                               float acc[8][4]) {
    const int rsel = lane & 15;
    const uint32_t koff = (uint32_t)((lane >> 4) << 4);
    #pragma unroll
    for (int kk = 0; kk < 4; kk++) {
        uint32_t rowkA = (uint32_t)(khalf * 4 + kk) * 32 + koff;
        uint32_t rowkB = (uint32_t)kk * 32 + koff;
        uint32_t bh[2][4], bl[2][4];
        #pragma unroll
        for (int nb = 0; nb < 2; nb++) {
            uint32_t boff = (uint32_t)(ng * 32 + nb * 16 + rsel) * LDW_B + rowkB;
            ldsm4(bh[nb], smb + whi + boff);
            ldsm4(bl[nb], smb + wlo + boff);
        }
        #pragma unroll
        for (int mt = 0; mt < 2; mt++) {
            uint32_t aoff = (uint32_t)(mg * 32 + mt * 16 + rsel) * LDB_B + rowkA;
            uint32_t ahi[4], alo[4];
            ldsm4(ahi, smb + SM_XHI + aoff);
            ldsm4(alo, smb + SM_XLO + aoff);
            #pragma unroll
            for (int nb = 0; nb < 2; nb++) {
                float* d0 = acc[mt * 4 + nb * 2];
                float* d1 = acc[mt * 4 + nb * 2 + 1];
                mma16816(d0, ahi, bh[nb][0], bh[nb][2]);
                mma16816(d1, ahi, bh[nb][1], bh[nb][3]);
                mma16816(d0, ahi, bl[nb][0], bl[nb][2]);
                mma16816(d1, ahi, bl[nb][1], bl[nb][3]);
                mma16816(d0, alo, bh[nb][0], bh[nb][2]);
                mma16816(d1, alo, bh[nb][1], bh[nb][3]);
            }
        }
    }
}

__global__ void __launch_bounds__(256, 2)
mlp_tc_kernel(const float* __restrict__ feat,           // residual source
              const uint4* __restrict__ xt,             // pre-split X tiles
              const uint4* __restrict__ wmat1, const uint4* __restrict__ wmat2,
              const float* __restrict__ b1, const float* __restrict__ b2,
              float* __restrict__ h_out, float* __restrict__ out, int N) {
    extern __shared__ char sm[];
    const uint32_t smb = smem_u32(sm);
    const int tid = threadIdx.x;
    const int wid = tid >> 5;
    const int lane = tid & 31;
    const int mg = wid & 1;            // 2 m-groups of 32 rows
    const int ng = wid >> 1;           // 4 n-groups of 32 cols
    const int row0 = blockIdx.x * BM;

    const float4* feat4 = (const float4*)feat;
    float* sB1 = (float*)(sm + SM_B1);
    float* sB2 = (float*)(sm + SM_B2);

    // group 0: X tiles (hi+lo contiguous, 2*XTILE_B bytes)
    {
        const uint4* xsrc = xt + (size_t)blockIdx.x * (2 * XTILE_B / 16);
        for (int i = tid; i < 2 * XTILE_B / 16; i += 256) {
            asm volatile("cp.async.cg.shared.global [%0], [%1], 16;"
                         :: "r"(smb + SM_XHI + (uint32_t)i * 16), "l"(xsrc + i));
        }
        asm volatile("cp.async.commit_group;" ::: "memory");
    }
    // group 1: W1h1, group 2: W1h2
    stage_whalf(smb, SM_WS0, SM_WS1, wmat1, tid);
    stage_whalf(smb, SM_WS2, SM_WS3, wmat1 + 2 * WHALF_U4, tid);

    if (tid < 128) {
        sB1[tid] = __ldg(b1 + tid);
        sB2[tid] = __ldg(b2 + tid);
    }

    float acc[8][4];
    #pragma unroll
    for (int t = 0; t < 8; t++)
        #pragma unroll
        for (int j = 0; j < 4; j++) acc[t][j] = 0.f;

    wait_cp_n<1>();          // X + W1h1 arrived
    __syncthreads();

    // ---- L1 half a (k 0..63) ----
    do_half(smb, SM_WS0, SM_WS1, 0, mg, ng, lane, acc);

    wait_cp_n<0>();          // W1h2 arrived
    __syncthreads();         // all warps done reading WS0/1
    stage_whalf(smb, SM_WS0, SM_WS1, wmat2, tid);   // W2h1 streams under L1b

    // ---- L1 half b (k 64..127) ----
    do_half(smb, SM_WS2, SM_WS3, 1, mg, ng, lane, acc);
    __syncthreads();         // all warps done reading X (and W1h2)

    // writeback h1 = leaky(acc + b1) into X tiles
    {
        const int c0 = 2 * (lane & 3);
        #pragma unroll
        for (int mt = 0; mt < 2; mt++) {
            const int r0 = mg * 32 + mt * 16 + (lane >> 2);
            #pragma unroll
            for (int nb = 0; nb < 2; nb++) {
                #pragma unroll
                for (int s = 0; s < 2; s++) {
                    int c = ng * 32 + nb * 16 + s * 8 + c0;
                    const float* a = acc[mt * 4 + nb * 2 + s];
                    float v0 = leaky(a[0] + sB1[c]);
                    float v1 = leaky(a[1] + sB1[c + 1]);
                    float v2 = leaky(a[2] + sB1[c]);
                    float v3 = leaky(a[3] + sB1[c + 1]);
                    uint32_t h01, l01, h23, l23;
                    split2(v0, v1, h01, l01);
                    split2(v2, v3, h23, l23);
                    uint32_t o0 = (uint32_t)r0 * LDB_B + (uint32_t)c * 2;
                    uint32_t o1 = o0 + 8u * LDB_B;
                    *(uint32_t*)(sm + SM_XHI + o0) = h01;
                    *(uint32_t*)(sm + SM_XLO + o0) = l01;
                    *(uint32_t*)(sm + SM_XHI + o1) = h23;
                    *(uint32_t*)(sm + SM_XLO + o1) = l23;
                }
            }
        }
    }

    #pragma unroll
    for (int t = 0; t < 8; t++)
        #pragma unroll
        for (int j = 0; j < 4; j++) acc[t][j] = 0.f;

    wait_cp_n<0>();          // W2h1 arrived
    __syncthreads();         // h1 writeback visible; W2h1 visible
    stage_whalf(smb, SM_WS2, SM_WS3, wmat2 + 2 * WHALF_U4, tid);  // W2h2 under L2a

    // ---- L2 half a ----
    do_half(smb, SM_WS0, SM_WS1, 0, mg, ng, lane, acc);

    wait_cp_n<0>();          // W2h2 arrived
    __syncthreads();
    // ---- L2 half b ----
    do_half(smb, SM_WS2, SM_WS3, 1, mg, ng, lane, acc);

    // epilogue staging (reuses WS0/1; all warps past L2a reads)
    __syncthreads();
    {
        float* fst = (float*)(sm + SM_FST);
        const int c0 = 2 * (lane & 3);
        #pragma unroll
        for (int mt = 0; mt < 2; mt++) {
            const int r0 = mg * 32 + mt * 16 + (lane >> 2);
            #pragma unroll
            for (int nb = 0; nb < 2; nb++) {
                #pragma unroll
                for (int s = 0; s < 2; s++) {
                    int c = ng * 32 + nb * 16 + s * 8 + c0;
                    const float* a = acc[mt * 4 + nb * 2 + s];
                    float v0 = leaky(a[0] + sB2[c]);
                    float v1 = leaky(a[1] + sB2[c + 1]);
                    float v2 = leaky(a[2] + sB2[c]);
                    float v3 = leaky(a[3] + sB2[c + 1]);
                    *(float2*)(fst + (size_t)r0 * LDF + c)       = make_float2(v0, v1);
                    *(float2*)(fst + (size_t)(r0 + 8) * LDF + c) = make_float2(v2, v3);
                }
            }
        }
    }
    __syncthreads();

    // coalesced final writes: out = h2 + feat; h_out = h2
    {
        const float* fst = (const float*)(sm + SM_FST);
        #pragma unroll
        for (int i = 0; i < 8; i++) {
            int idx = tid + i * 256;
            int r = idx >> 5, c4 = idx & 31;
            int grow = row0 + r;
            if (grow >= N) continue;
            const float* p = fst + (size_t)r * LDF + c4 * 4;
            float4 h = make_float4(p[0], p[1], p[2], p[3]);
            float4 fv = __ldg(feat4 + (size_t)grow * 32 + c4);
            ((float4*)out)[(size_t)grow * 32 + c4] =
                make_float4(h.x + fv.x, h.y + fv.y, h.z + fv.z, h.w + fv.w);
            if (h_out)
                ((float4*)h_out)[(size_t)grow * 32 + c4] = h;
        }
    }
}

extern "C" void kernel_launch(void* const* d_in, const int* in_sizes, int n_in,
                              void* d_out, int out_size) {
    const float* feat_row = (const float*)d_in[0];
    const float* feat_col = (const float*)d_in[1];
    const int*   src_c2r  = (const int*)d_in[2];
    const int*   dst_c2r  = (const int*)d_in[3];
    const float* w_c2r    = (const float*)d_in[4];
    const int*   src_r2c  = (const int*)d_in[5];
    const int*   dst_r2c  = (const int*)d_in[6];
    const float* w_r2c    = (const float*)d_in[7];
    const float* W1_c2r   = (const float*)d_in[8];
    const float* b1_c2r   = (const float*)d_in[9];
    const float* W2_c2r   = (const float*)d_in[10];
    const float* b2_c2r   = (const float*)d_in[11];
    const float* W1_r2c   = (const float*)d_in[12];
    const float* b1_r2c   = (const float*)d_in[13];
    const float* W2_r2c   = (const float*)d_in[14];
    const float* b2_r2c   = (const float*)d_in[15];
    const float* eps_c2r  = (const float*)d_in[16];
    const float* eps_r2c  = (const float*)d_in[17];

    const int E = in_sizes[2];

    float* out_row = (float*)d_out;
    float* out_col = out_row + (size_t)NROW * D;

    float* hrow;
    uint4 *wt, *xt;
    int *cnt, *ptr, *bsum, *flag;
    int2* edges;
    cudaGetSymbolAddress((void**)&hrow,  g_hrow);
    cudaGetSymbolAddress((void**)&wt,    g_wt);
    cudaGetSymbolAddress((void**)&xt,    g_xt);
    cudaGetSymbolAddress((void**)&cnt,   g_cnt);
    cudaGetSymbolAddress((void**)&ptr,   g_ptr);
    cudaGetSymbolAddress((void**)&bsum,  g_bsum);
    cudaGetSymbolAddress((void**)&flag,  g_flag);
    cudaGetSymbolAddress((void**)&edges, g_edges);

    const int MAT_U4 = 2 * 2 * WHALF_U4;
    const uint4* w1_a = wt + 0 * MAT_U4;
    const uint4* w2_a = wt + 1 * MAT_U4;
    const uint4* w1_b = wt + 2 * MAT_U4;
    const uint4* w2_b = wt + 3 * MAT_U4;

    cudaFuncSetAttribute(mlp_tc_kernel, cudaFuncAttributeMaxDynamicSharedMemorySize, SM_TOTAL);

    const int e2grid = (2 * E + 255) / 256;
    const int g_row = (NROW + BM - 1) / BM;
    const int g_col = (NCOL + BM - 1) / BM;
    const int nscan_blocks = (NTOT + 1023) / 1024;
    const int agg_grid = (NROW * 32 + 255) / 256;

    // ---- CSR build (4 launches) ----
    prep_kernel<<<32, 256>>>(W1_c2r, W2_c2r, W1_r2c, W2_r2c, cnt, flag);
    hist2_kernel<<<e2grid, 256>>>(dst_c2r, dst_r2c, cnt, E);
    scan_blk_kernel<<<nscan_blocks, 1024>>>(cnt, ptr, bsum, flag, NTOT);
    scatter2_kernel<<<e2grid, 256>>>(src_c2r, dst_c2r, w_c2r, src_r2c, dst_r2c, w_r2c,
                                     ptr, bsum, cnt, edges, E);

    // ---- col -> row ----
    csr_agg_kernel<<<agg_grid, 256>>>((const float4*)feat_col, (const float4*)feat_row,
                                      ptr, bsum, edges, xt, eps_c2r, NROW, 0);
    mlp_tc_kernel<<<g_row, 256, SM_TOTAL>>>(feat_row, xt, w1_a, w2_a,
                                            b1_c2r, b2_c2r, hrow, out_row, NROW);
    // ---- row -> col (gathers from updated h_row) ----
    csr_agg_kernel<<<agg_grid, 256>>>((const float4*)hrow, (const float4*)feat_col,
                                      ptr, bsum, edges, xt, eps_r2c, NCOL, NROW);
    mlp_tc_kernel<<<g_col, 256, SM_TOTAL>>>(feat_col, xt, w1_b, w2_b,
                                            b1_r2c, b2_r2c, nullptr, out_col, NCOL);
}